// round 1
// baseline (speedup 1.0000x reference)
#include <cuda_runtime.h>
#include <cstdint>

// Problem constants
#define L_SEQ 2048
#define NBATCH 4
#define EMB 1024
#define NHEAD 16
#define HDIM 64
#define BH (NBATCH*NHEAD)          // 64
#define MROWS (L_SEQ*NBATCH)       // 8192
#define SCALING 0.125f

// Scratch (device globals; allocation-free per harness rules)
__device__ float g_q [BH * L_SEQ * HDIM];        // [bh, l, d]
__device__ float g_k [BH * L_SEQ * HDIM];        // [bh, s, d]
__device__ float g_vt[BH * HDIM * L_SEQ];        // [bh, d, s]  (transposed V)
__device__ float g_ctx[MROWS * EMB];             // [l*4+n, e]
__device__ float g_P[(size_t)BH * L_SEQ * L_SEQ]; // [bh, l, s] attention probs (1.07 GB)

// ---------------------------------------------------------------------------
// Generic tile core: C[m,n] = sum_k A[m*K+k] * B[n*K+k]   (A @ B^T, both K-major)
// Exact-divisibility assumed (all shapes here are multiples of tiles).
// ---------------------------------------------------------------------------
template<int BM,int BN,int BK,int TM,int TN,int NT>
__device__ __forceinline__ void gemm_tile_abt(
    const float* __restrict__ A, const float* __restrict__ B,
    int K, int m0, int n0, float acc[TM][TN])
{
    __shared__ float As[BK][BM];
    __shared__ float Bs[BK][BN];
    const int tid = threadIdx.x;
    const int tx  = tid % (BN/TN);
    const int ty  = tid / (BN/TN);

    #pragma unroll
    for (int i = 0; i < TM; i++)
        #pragma unroll
        for (int j = 0; j < TN; j++) acc[i][j] = 0.f;

    for (int k0 = 0; k0 < K; k0 += BK) {
        #pragma unroll
        for (int idx = tid; idx < BM*BK/4; idx += NT) {
            int row = idx / (BK/4);
            int kc  = (idx % (BK/4)) * 4;
            float4 v = *reinterpret_cast<const float4*>(&A[(size_t)(m0+row)*K + k0 + kc]);
            As[kc+0][row] = v.x; As[kc+1][row] = v.y;
            As[kc+2][row] = v.z; As[kc+3][row] = v.w;
        }
        #pragma unroll
        for (int idx = tid; idx < BN*BK/4; idx += NT) {
            int row = idx / (BK/4);
            int kc  = (idx % (BK/4)) * 4;
            float4 v = *reinterpret_cast<const float4*>(&B[(size_t)(n0+row)*K + k0 + kc]);
            Bs[kc+0][row] = v.x; Bs[kc+1][row] = v.y;
            Bs[kc+2][row] = v.z; Bs[kc+3][row] = v.w;
        }
        __syncthreads();
        #pragma unroll
        for (int k = 0; k < BK; k++) {
            float a[TM], b[TN];
            #pragma unroll
            for (int i = 0; i < TM; i++) a[i] = As[k][ty*TM + i];
            #pragma unroll
            for (int j = 0; j < TN; j++) b[j] = Bs[k][tx*TN + j];
            #pragma unroll
            for (int i = 0; i < TM; i++)
                #pragma unroll
                for (int j = 0; j < TN; j++) acc[i][j] += a[i] * b[j];
        }
        __syncthreads();
    }
}

// ---------------------------------------------------------------------------
// K1: QKV projections.  X[m, k] @ W[e, k]^T + b[e]; scatter to head-major.
// grid (EMB/128, MROWS/128, 3), 256 threads
// ---------------------------------------------------------------------------
__global__ __launch_bounds__(256)
void qkv_proj_kernel(const float* __restrict__ xq, const float* __restrict__ xk,
                     const float* __restrict__ xv,
                     const float* __restrict__ Wq, const float* __restrict__ Wk,
                     const float* __restrict__ Wv,
                     const float* __restrict__ bq, const float* __restrict__ bk,
                     const float* __restrict__ bv)
{
    constexpr int BM=128, BN=128, BK=16, TM=8, TN=8, NT=256;
    const int z = blockIdx.z;
    const float* A    = (z==0) ? xq : (z==1) ? xk : xv;
    const float* B    = (z==0) ? Wq : (z==1) ? Wk : Wv;
    const float* bias = (z==0) ? bq : (z==1) ? bk : bv;

    const int m0 = blockIdx.y * BM;
    const int n0 = blockIdx.x * BN;
    float acc[TM][TN];
    gemm_tile_abt<BM,BN,BK,TM,TN,NT>(A, B, EMB, m0, n0, acc);

    const int tx = threadIdx.x % (BN/TN);
    const int ty = threadIdx.x / (BN/TN);
    #pragma unroll
    for (int i = 0; i < TM; i++) {
        const int m = m0 + ty*TM + i;
        const int l = m >> 2, n = m & 3;
        #pragma unroll
        for (int j = 0; j < TN; j++) {
            const int e = n0 + tx*TN + j;
            const int h = e >> 6, d = e & 63;
            const int bh = n*NHEAD + h;
            float v = acc[i][j] + bias[e];
            if (z == 0)      g_q [((size_t)bh*L_SEQ + l)*HDIM + d] = v * SCALING;
            else if (z == 1) g_k [((size_t)bh*L_SEQ + l)*HDIM + d] = v;
            else             g_vt[((size_t)bh*HDIM + d)*L_SEQ + l] = v;
        }
    }
}

// ---------------------------------------------------------------------------
// K2: scores P[bh, l, s] = q[bh,l,:] . k[bh,s,:]
// grid (L/128, L/128, BH), 256 threads
// ---------------------------------------------------------------------------
__global__ __launch_bounds__(256)
void scores_kernel()
{
    constexpr int BM=128, BN=128, BK=16, TM=8, TN=8, NT=256;
    const int bh = blockIdx.z;
    const float* A = g_q + (size_t)bh * L_SEQ * HDIM;
    const float* B = g_k + (size_t)bh * L_SEQ * HDIM;
    const int m0 = blockIdx.y * BM;
    const int n0 = blockIdx.x * BN;
    float acc[TM][TN];
    gemm_tile_abt<BM,BN,BK,TM,TN,NT>(A, B, HDIM, m0, n0, acc);

    float* P = g_P + (size_t)bh * L_SEQ * L_SEQ;
    const int tx = threadIdx.x % (BN/TN);
    const int ty = threadIdx.x / (BN/TN);
    #pragma unroll
    for (int i = 0; i < TM; i++) {
        const int m = m0 + ty*TM + i;
        #pragma unroll
        for (int j = 0; j < TN; j++) {
            const int n = n0 + tx*TN + j;
            P[(size_t)m * L_SEQ + n] = acc[i][j];
        }
    }
}

// ---------------------------------------------------------------------------
// K3: row softmax of P (in place). grid (L, BH), 256 threads; 8 elems/thread.
// ---------------------------------------------------------------------------
__global__ __launch_bounds__(256)
void softmax_kernel()
{
    const int t = threadIdx.x;
    float* p = g_P + ((size_t)blockIdx.y * L_SEQ + blockIdx.x) * L_SEQ;
    float v[8];
    float m = -1e30f;
    #pragma unroll
    for (int i = 0; i < 8; i++) { v[i] = p[t + 256*i]; m = fmaxf(m, v[i]); }

    __shared__ float red[8];
    #pragma unroll
    for (int o = 16; o; o >>= 1) m = fmaxf(m, __shfl_xor_sync(0xffffffffu, m, o));
    if ((t & 31) == 0) red[t >> 5] = m;
    __syncthreads();
    if (t < 32) {
        float w = (t < 8) ? red[t] : -1e30f;
        #pragma unroll
        for (int o = 4; o; o >>= 1) w = fmaxf(w, __shfl_xor_sync(0xffffffffu, w, o));
        if (t == 0) red[0] = w;
    }
    __syncthreads();
    m = red[0];

    float s = 0.f;
    #pragma unroll
    for (int i = 0; i < 8; i++) { v[i] = __expf(v[i] - m); s += v[i]; }
    __syncthreads();
    #pragma unroll
    for (int o = 16; o; o >>= 1) s += __shfl_xor_sync(0xffffffffu, s, o);
    if ((t & 31) == 0) red[t >> 5] = s;
    __syncthreads();
    if (t < 32) {
        float w = (t < 8) ? red[t] : 0.f;
        #pragma unroll
        for (int o = 4; o; o >>= 1) w += __shfl_xor_sync(0xffffffffu, w, o);
        if (t == 0) red[0] = w;
    }
    __syncthreads();
    const float inv = 1.0f / red[0];
    #pragma unroll
    for (int i = 0; i < 8; i++) p[t + 256*i] = v[i] * inv;
}

// ---------------------------------------------------------------------------
// K4: avg_weights[n, l, s] = (1/16) * sum_h P[n*16+h, l, s]
// grid (L, NBATCH), 256 threads; 8 cols/thread
// ---------------------------------------------------------------------------
__global__ __launch_bounds__(256)
void avg_kernel(float* __restrict__ avg)
{
    const int l = blockIdx.x, n = blockIdx.y, t = threadIdx.x;
    #pragma unroll
    for (int i = 0; i < 8; i++) {
        const int s = t + 256*i;
        float acc = 0.f;
        #pragma unroll
        for (int h = 0; h < NHEAD; h++)
            acc += g_P[(((size_t)(n*NHEAD + h))*L_SEQ + l)*L_SEQ + s];
        avg[((size_t)n * L_SEQ + l)*L_SEQ + s] = acc * (1.0f/NHEAD);
    }
}

// ---------------------------------------------------------------------------
// K5: ctx = P @ V  (via transposed V: C[l,d] = sum_s P[l,s] * Vt[d,s])
// grid (HDIM/64, L/128, BH), 128 threads
// ---------------------------------------------------------------------------
__global__ __launch_bounds__(128)
void pv_kernel()
{
    constexpr int BM=128, BN=64, BK=16, TM=8, TN=8, NT=128;
    const int bh = blockIdx.z;
    const float* A = g_P  + (size_t)bh * L_SEQ * L_SEQ;
    const float* B = g_vt + (size_t)bh * HDIM * L_SEQ;
    const int m0 = blockIdx.y * BM;
    const int n0 = blockIdx.x * BN;
    float acc[TM][TN];
    gemm_tile_abt<BM,BN,BK,TM,TN,NT>(A, B, L_SEQ, m0, n0, acc);

    const int nb = bh / NHEAD;    // batch
    const int h  = bh % NHEAD;    // head
    const int tx = threadIdx.x % (BN/TN);
    const int ty = threadIdx.x / (BN/TN);
    #pragma unroll
    for (int i = 0; i < TM; i++) {
        const int l = m0 + ty*TM + i;
        #pragma unroll
        for (int j = 0; j < TN; j++) {
            const int d = n0 + tx*TN + j;
            g_ctx[((size_t)(l*NBATCH + nb))*EMB + h*HDIM + d] = acc[i][j];
        }
    }
}

// ---------------------------------------------------------------------------
// K6: attn_output = ctx @ Wo^T + bo   -> d_out[0 : 8388608)
// grid (EMB/128, MROWS/128), 256 threads
// ---------------------------------------------------------------------------
__global__ __launch_bounds__(256)
void outproj_kernel(const float* __restrict__ Wo, const float* __restrict__ bo,
                    float* __restrict__ out)
{
    constexpr int BM=128, BN=128, BK=16, TM=8, TN=8, NT=256;
    const int m0 = blockIdx.y * BM;
    const int n0 = blockIdx.x * BN;
    float acc[TM][TN];
    gemm_tile_abt<BM,BN,BK,TM,TN,NT>(g_ctx, Wo, EMB, m0, n0, acc);

    const int tx = threadIdx.x % (BN/TN);
    const int ty = threadIdx.x / (BN/TN);
    #pragma unroll
    for (int i = 0; i < TM; i++) {
        const int m = m0 + ty*TM + i;
        #pragma unroll
        for (int j = 0; j < TN; j++) {
            const int e = n0 + tx*TN + j;
            out[(size_t)m * EMB + e] = acc[i][j] + bo[e];
        }
    }
}

// ---------------------------------------------------------------------------
extern "C" void kernel_launch(void* const* d_in, const int* in_sizes, int n_in,
                              void* d_out, int out_size)
{
    const float* query = (const float*)d_in[0];
    const float* key   = (const float*)d_in[1];
    const float* value = (const float*)d_in[2];
    const float* Wq    = (const float*)d_in[3];
    const float* bq    = (const float*)d_in[4];
    const float* Wk    = (const float*)d_in[5];
    const float* bk    = (const float*)d_in[6];
    const float* Wv    = (const float*)d_in[7];
    const float* bv    = (const float*)d_in[8];
    const float* Wo    = (const float*)d_in[9];
    const float* bo    = (const float*)d_in[10];

    float* out = (float*)d_out;                          // [L, N, E]
    float* avg = out + (size_t)L_SEQ * NBATCH * EMB;     // [N, L, S]

    qkv_proj_kernel<<<dim3(EMB/128, MROWS/128, 3), 256>>>(query, key, value,
                                                          Wq, Wk, Wv, bq, bk, bv);
    scores_kernel <<<dim3(L_SEQ/128, L_SEQ/128, BH), 256>>>();
    softmax_kernel<<<dim3(L_SEQ, BH), 256>>>();
    avg_kernel    <<<dim3(L_SEQ, NBATCH), 256>>>(avg);
    pv_kernel     <<<dim3(HDIM/64, L_SEQ/128, BH), 128>>>();
    outproj_kernel<<<dim3(EMB/128, MROWS/128), 256>>>(Wo, bo, out);
}

// round 3
// speedup vs baseline: 3.1695x; 3.1695x over previous
#include <cuda_runtime.h>
#include <cstdint>

#define L_SEQ 2048
#define NBATCH 4
#define EMB 1024
#define NHEAD 16
#define HDIM 64
#define BH (NBATCH*NHEAD)
#define MROWS (L_SEQ*NBATCH)
#define SCALING 0.125f

// Scratch (device globals; allocation-free per harness rules)
__device__ float g_q  [BH * L_SEQ * HDIM];          // [bh, l, d] (pre-scaled)
__device__ float g_k  [BH * L_SEQ * HDIM];          // [bh, s, d]
__device__ float g_vt [BH * HDIM * L_SEQ];          // [bh, d, s] (transposed V)
__device__ float g_ctx[MROWS * EMB];                // [l*4+n, e]
__device__ float g_P  [(size_t)BH * L_SEQ * L_SEQ]; // [bh, l, s]

// ===========================================================================
// tf32 helpers (base sm_103 target — NO tcgen05, mma.sync HMMA path only)
// ===========================================================================
__device__ __forceinline__ uint32_t f2tf32(float f){
    uint32_t r; asm("cvt.rna.tf32.f32 %0, %1;" : "=r"(r) : "f"(f)); return r;
}
__device__ __forceinline__ void mma8(float* c, const uint32_t* a, uint32_t b0, uint32_t b1){
    asm volatile("mma.sync.aligned.m16n8k8.row.col.f32.tf32.tf32.f32 "
        "{%0,%1,%2,%3},{%4,%5,%6,%7},{%8,%9},{%0,%1,%2,%3};"
        : "+f"(c[0]), "+f"(c[1]), "+f"(c[2]), "+f"(c[3])
        : "r"(a[0]), "r"(a[1]), "r"(a[2]), "r"(a[3]), "r"(b0), "r"(b1));
}

// ===========================================================================
// Staging: K-chunks of 32 floats/row, tf32-converted, XOR-swizzled smem.
// smem row pitch = 32 floats; granule (4 floats) index ^= (row & 7).
// Fragment loads are bank-conflict-free; v4 stores run at crossbar floor.
// ===========================================================================
template<int ROWS>
__device__ __forceinline__ void ldg_chunk(float4* rv, const float* __restrict__ src,
                                          int ld, int k0, int tid){
    const int r0 = tid >> 3, g = tid & 7;
    #pragma unroll
    for (int p = 0; p < ROWS/32; p++){
        const int row = r0 + 32*p;
        rv[p] = *reinterpret_cast<const float4*>(src + (size_t)row*ld + k0 + g*4);
    }
}
template<int ROWS>
__device__ __forceinline__ void sts_chunk(float* dst, const float4* rv, int tid){
    const int r0 = tid >> 3, g = tid & 7;
    #pragma unroll
    for (int p = 0; p < ROWS/32; p++){
        const int row = r0 + 32*p;
        uint4 w;
        w.x = f2tf32(rv[p].x); w.y = f2tf32(rv[p].y);
        w.z = f2tf32(rv[p].z); w.w = f2tf32(rv[p].w);
        *reinterpret_cast<uint4*>(dst + row*32 + ((g ^ (row & 7)) << 2)) = w;
    }
}

// ===========================================================================
// Compute one staged K-chunk (32). Warp grid 4(m) x 2(n); warp tile 32 x BN/2.
// ===========================================================================
template<int BN>
__device__ __forceinline__ void gemm_compute(const float* As, const float* Bs,
        float acc[2][BN/16][4], int grp, int tig, int wm, int wn){
    constexpr int NT = BN/16;
    #pragma unroll
    for (int s = 0; s < 4; s++){
        uint32_t afr[2][4];
        #pragma unroll
        for (int mi = 0; mi < 2; mi++){
            const int r0 = wm*32 + mi*16 + grp;
            const int r1 = r0 + 8;                     // (r1&7)==(r0&7)
            const int g0 = ((2*s)     ^ (r0 & 7)) << 2;
            const int g1 = ((2*s + 1) ^ (r0 & 7)) << 2;
            afr[mi][0] = __float_as_uint(As[r0*32 + g0 + tig]);
            afr[mi][1] = __float_as_uint(As[r1*32 + g0 + tig]);
            afr[mi][2] = __float_as_uint(As[r0*32 + g1 + tig]);
            afr[mi][3] = __float_as_uint(As[r1*32 + g1 + tig]);
        }
        #pragma unroll
        for (int ni = 0; ni < NT; ni++){
            const int n  = wn*(BN/2) + ni*8 + grp;
            const int g0 = ((2*s)     ^ (n & 7)) << 2;
            const int g1 = ((2*s + 1) ^ (n & 7)) << 2;
            const uint32_t b0 = __float_as_uint(Bs[n*32 + g0 + tig]);
            const uint32_t b1 = __float_as_uint(Bs[n*32 + g1 + tig]);
            mma8(acc[0][ni], afr[0], b0, b1);
            mma8(acc[1][ni], afr[1], b0, b1);
        }
    }
}

// ===========================================================================
// Full GEMM driver: C(128 x BN) += A(128 x K, K-major) @ B(BN x K, K-major)^T
// Double-buffered chunks, one __syncthreads per chunk.
// ===========================================================================
template<int BN>
__device__ __forceinline__ void gemm_run(float* smem,
        const float* __restrict__ A, int lda,
        const float* __restrict__ B, int ldb,
        int K, float acc[2][BN/16][4]){
    const int tid = threadIdx.x;
    constexpr int AF = 128*32, BF = BN*32, BUF = AF + BF;
    const int lane = tid & 31, grp = lane >> 2, tig = lane & 3;
    const int warp = tid >> 5, wm = warp & 3, wn = warp >> 2;

    float4 ra[4], rb[4];
    ldg_chunk<128>(ra, A, lda, 0, tid);
    ldg_chunk<BN >(rb, B, ldb, 0, tid);
    sts_chunk<128>(smem,      ra, tid);
    sts_chunk<BN >(smem + AF, rb, tid);
    __syncthreads();

    const int nc = K / 32;
    for (int c = 0; c < nc; c++){
        if (c + 1 < nc){
            ldg_chunk<128>(ra, A, lda, (c+1)*32, tid);
            ldg_chunk<BN >(rb, B, ldb, (c+1)*32, tid);
        }
        float* cur = smem + (c & 1)*BUF;
        gemm_compute<BN>(cur, cur + AF, acc, grp, tig, wm, wn);
        if (c + 1 < nc){
            float* nxt = smem + ((c+1) & 1)*BUF;
            sts_chunk<128>(nxt,      ra, tid);
            sts_chunk<BN >(nxt + AF, rb, tid);
            __syncthreads();
        }
    }
}

// ===========================================================================
// K1: QKV projections. z = 0/1/2 -> q/k/v. q pre-scaled; v stored transposed.
// grid (8, 64, 3), 256 threads
// ===========================================================================
__global__ __launch_bounds__(256)
void k_qkv(const float* __restrict__ xq, const float* __restrict__ xk,
           const float* __restrict__ xv,
           const float* __restrict__ Wq, const float* __restrict__ Wk,
           const float* __restrict__ Wv,
           const float* __restrict__ bq, const float* __restrict__ bk,
           const float* __restrict__ bv){
    extern __shared__ float smem[];
    const int z = blockIdx.z;
    const float* X    = (z==0) ? xq : (z==1) ? xk : xv;
    const float* W    = (z==0) ? Wq : (z==1) ? Wk : Wv;
    const float* bias = (z==0) ? bq : (z==1) ? bk : bv;
    const int m0 = blockIdx.y*128, n0 = blockIdx.x*128;

    float acc[2][8][4];
    #pragma unroll
    for (int i = 0; i < 2; i++)
        #pragma unroll
        for (int j = 0; j < 8; j++)
            #pragma unroll
            for (int q = 0; q < 4; q++) acc[i][j][q] = 0.f;

    gemm_run<128>(smem, X + (size_t)m0*EMB, EMB, W + (size_t)n0*EMB, EMB, EMB, acc);

    const int lane = threadIdx.x & 31, grp = lane >> 2, tig = lane & 3;
    const int warp = threadIdx.x >> 5, wm = warp & 3, wn = warp >> 2;
    #pragma unroll
    for (int mi = 0; mi < 2; mi++){
        #pragma unroll
        for (int ni = 0; ni < 8; ni++){
            const int col = wn*64 + ni*8 + tig*2;
            const int e = n0 + col, h = e >> 6, d = e & 63;
            const float b0v = bias[e], b1v = bias[e+1];
            #pragma unroll
            for (int half = 0; half < 2; half++){
                const int row = wm*32 + mi*16 + grp + half*8;
                const int m = m0 + row, l = m >> 2, nb = m & 3;
                const int bh = nb*NHEAD + h;
                const float c0 = acc[mi][ni][half*2] + b0v;
                const float c1 = acc[mi][ni][half*2+1] + b1v;
                if (z == 0){
                    *reinterpret_cast<float2*>(&g_q[((size_t)bh*L_SEQ + l)*HDIM + d]) =
                        make_float2(c0*SCALING, c1*SCALING);
                } else if (z == 1){
                    *reinterpret_cast<float2*>(&g_k[((size_t)bh*L_SEQ + l)*HDIM + d]) =
                        make_float2(c0, c1);
                } else {
                    g_vt[((size_t)bh*HDIM + d    )*L_SEQ + l] = c0;
                    g_vt[((size_t)bh*HDIM + d + 1)*L_SEQ + l] = c1;
                }
            }
        }
    }
}

// ===========================================================================
// K2: raw scores P[bh,l,s] = q . k.  grid (16,16,64), 256 threads
// ===========================================================================
__global__ __launch_bounds__(256)
void k_scores(){
    extern __shared__ float smem[];
    const int bh = blockIdx.z, m0 = blockIdx.y*128, n0 = blockIdx.x*128;

    float acc[2][8][4];
    #pragma unroll
    for (int i = 0; i < 2; i++)
        #pragma unroll
        for (int j = 0; j < 8; j++)
            #pragma unroll
            for (int q = 0; q < 4; q++) acc[i][j][q] = 0.f;

    gemm_run<128>(smem, g_q + ((size_t)bh*L_SEQ + m0)*HDIM, HDIM,
                        g_k + ((size_t)bh*L_SEQ + n0)*HDIM, HDIM, HDIM, acc);

    float* P = g_P + (size_t)bh*L_SEQ*L_SEQ;
    const int lane = threadIdx.x & 31, grp = lane >> 2, tig = lane & 3;
    const int warp = threadIdx.x >> 5, wm = warp & 3, wn = warp >> 2;
    #pragma unroll
    for (int mi = 0; mi < 2; mi++)
        #pragma unroll
        for (int ni = 0; ni < 8; ni++){
            const int col = n0 + wn*64 + ni*8 + tig*2;
            #pragma unroll
            for (int half = 0; half < 2; half++){
                const int row = m0 + wm*32 + mi*16 + grp + half*8;
                *reinterpret_cast<float2*>(&P[(size_t)row*L_SEQ + col]) =
                    make_float2(acc[mi][ni][half*2], acc[mi][ni][half*2+1]);
            }
        }
}

// ===========================================================================
// K3: fused softmax (in place) + head-average.  grid (L, NBATCH), 256 thr.
// Block (l, n) processes 16 head rows, accumulates avg in registers.
// ===========================================================================
__global__ __launch_bounds__(256)
void k_softmax_avg(float* __restrict__ avg){
    const int l = blockIdx.x, n = blockIdx.y, t = threadIdx.x;
    __shared__ float red[8];
    float asum[8];
    #pragma unroll
    for (int i = 0; i < 8; i++) asum[i] = 0.f;

    for (int h = 0; h < NHEAD; h++){
        float* p = g_P + (((size_t)(n*NHEAD + h))*L_SEQ + l)*L_SEQ;
        float v[8];
        float m = -1e30f;
        #pragma unroll
        for (int i = 0; i < 8; i++){ v[i] = p[t + 256*i]; m = fmaxf(m, v[i]); }

        #pragma unroll
        for (int o = 16; o; o >>= 1) m = fmaxf(m, __shfl_xor_sync(0xffffffffu, m, o));
        if ((t & 31) == 0) red[t >> 5] = m;
        __syncthreads();
        if (t < 32){
            float w = (t < 8) ? red[t] : -1e30f;
            #pragma unroll
            for (int o = 4; o; o >>= 1) w = fmaxf(w, __shfl_xor_sync(0xffffffffu, w, o));
            if (t == 0) red[0] = w;
        }
        __syncthreads();
        m = red[0];
        __syncthreads();

        float s = 0.f;
        #pragma unroll
        for (int i = 0; i < 8; i++){ v[i] = __expf(v[i] - m); s += v[i]; }
        #pragma unroll
        for (int o = 16; o; o >>= 1) s += __shfl_xor_sync(0xffffffffu, s, o);
        if ((t & 31) == 0) red[t >> 5] = s;
        __syncthreads();
        if (t < 32){
            float w = (t < 8) ? red[t] : 0.f;
            #pragma unroll
            for (int o = 4; o; o >>= 1) w += __shfl_xor_sync(0xffffffffu, w, o);
            if (t == 0) red[0] = w;
        }
        __syncthreads();
        const float inv = 1.0f / red[0];
        __syncthreads();
        #pragma unroll
        for (int i = 0; i < 8; i++){
            const float pv = v[i] * inv;
            p[t + 256*i] = pv;
            asum[i] += pv;
        }
    }
    #pragma unroll
    for (int i = 0; i < 8; i++)
        avg[((size_t)n*L_SEQ + l)*L_SEQ + t + 256*i] = asum[i] * (1.0f/NHEAD);
}

// ===========================================================================
// K5: ctx = P @ V (vt is [bh, d, s] so B is K-major directly). BN=64.
// grid (16, 64), 256 threads
// ===========================================================================
__global__ __launch_bounds__(256)
void k_pv(){
    extern __shared__ float smem[];
    const int m0 = blockIdx.x*128, bh = blockIdx.y;
    const int nb = bh >> 4, h = bh & 15;

    float acc[2][4][4];
    #pragma unroll
    for (int i = 0; i < 2; i++)
        #pragma unroll
        for (int j = 0; j < 4; j++)
            #pragma unroll
            for (int q = 0; q < 4; q++) acc[i][j][q] = 0.f;

    gemm_run<64>(smem, g_P  + (size_t)bh*L_SEQ*L_SEQ + (size_t)m0*L_SEQ, L_SEQ,
                       g_vt + (size_t)bh*HDIM*L_SEQ, L_SEQ, L_SEQ, acc);

    const int lane = threadIdx.x & 31, grp = lane >> 2, tig = lane & 3;
    const int warp = threadIdx.x >> 5, wm = warp & 3, wn = warp >> 2;
    #pragma unroll
    for (int mi = 0; mi < 2; mi++)
        #pragma unroll
        for (int ni = 0; ni < 4; ni++){
            const int d = wn*32 + ni*8 + tig*2;
            #pragma unroll
            for (int half = 0; half < 2; half++){
                const int row = wm*32 + mi*16 + grp + half*8;
                const int l = m0 + row;
                *reinterpret_cast<float2*>(&g_ctx[((size_t)(l*NBATCH + nb))*EMB + h*HDIM + d]) =
                    make_float2(acc[mi][ni][half*2], acc[mi][ni][half*2+1]);
            }
        }
}

// ===========================================================================
// K6: attn_output = ctx @ Wo^T + bo.  grid (8, 64), 256 threads
// ===========================================================================
__global__ __launch_bounds__(256)
void k_out(const float* __restrict__ Wo, const float* __restrict__ bo,
           float* __restrict__ out){
    extern __shared__ float smem[];
    const int m0 = blockIdx.y*128, n0 = blockIdx.x*128;

    float acc[2][8][4];
    #pragma unroll
    for (int i = 0; i < 2; i++)
        #pragma unroll
        for (int j = 0; j < 8; j++)
            #pragma unroll
            for (int q = 0; q < 4; q++) acc[i][j][q] = 0.f;

    gemm_run<128>(smem, g_ctx + (size_t)m0*EMB, EMB, Wo + (size_t)n0*EMB, EMB, EMB, acc);

    const int lane = threadIdx.x & 31, grp = lane >> 2, tig = lane & 3;
    const int warp = threadIdx.x >> 5, wm = warp & 3, wn = warp >> 2;
    #pragma unroll
    for (int mi = 0; mi < 2; mi++)
        #pragma unroll
        for (int ni = 0; ni < 8; ni++){
            const int col = n0 + wn*64 + ni*8 + tig*2;
            const float b0v = bo[col], b1v = bo[col+1];
            #pragma unroll
            for (int half = 0; half < 2; half++){
                const int row = m0 + wm*32 + mi*16 + grp + half*8;
                *reinterpret_cast<float2*>(&out[(size_t)row*EMB + col]) =
                    make_float2(acc[mi][ni][half*2] + b0v, acc[mi][ni][half*2+1] + b1v);
            }
        }
}

// ===========================================================================
#define SMEM128 (2*(128*32 + 128*32)*4)   // 65536 bytes
#define SMEM64  (2*(128*32 +  64*32)*4)   // 49152 bytes

extern "C" void kernel_launch(void* const* d_in, const int* in_sizes, int n_in,
                              void* d_out, int out_size)
{
    const float* query = (const float*)d_in[0];
    const float* key   = (const float*)d_in[1];
    const float* value = (const float*)d_in[2];
    const float* Wq    = (const float*)d_in[3];
    const float* bq    = (const float*)d_in[4];
    const float* Wk    = (const float*)d_in[5];
    const float* bk    = (const float*)d_in[6];
    const float* Wv    = (const float*)d_in[7];
    const float* bv    = (const float*)d_in[8];
    const float* Wo    = (const float*)d_in[9];
    const float* bo    = (const float*)d_in[10];

    float* out = (float*)d_out;                          // [L, N, E]
    float* avg = out + (size_t)L_SEQ * NBATCH * EMB;     // [N, L, S]

    static int configured = 0;
    if (!configured){
        cudaFuncSetAttribute(k_qkv,    cudaFuncAttributeMaxDynamicSharedMemorySize, SMEM128);
        cudaFuncSetAttribute(k_scores, cudaFuncAttributeMaxDynamicSharedMemorySize, SMEM128);
        cudaFuncSetAttribute(k_out,    cudaFuncAttributeMaxDynamicSharedMemorySize, SMEM128);
        cudaFuncSetAttribute(k_pv,     cudaFuncAttributeMaxDynamicSharedMemorySize, SMEM64);
        configured = 1;
    }

    k_qkv        <<<dim3(EMB/128, MROWS/128, 3), 256, SMEM128>>>(query, key, value,
                                                                 Wq, Wk, Wv, bq, bk, bv);
    k_scores     <<<dim3(L_SEQ/128, L_SEQ/128, BH), 256, SMEM128>>>();
    k_softmax_avg<<<dim3(L_SEQ, NBATCH), 256>>>(avg);
    k_pv         <<<dim3(L_SEQ/128, BH), 256, SMEM64>>>();
    k_out        <<<dim3(EMB/128, MROWS/128), 256, SMEM128>>>(Wo, bo, out);
}